// round 13
// baseline (speedup 1.0000x reference)
#include <cuda_runtime.h>
#include <cuda_fp16.h>
#include <math.h>
#include <stdint.h>

#define T_TOK 2048
#define H_DIM 2048
#define E_NUM 32
#define I_DIM 768
#define TOPK  8
#define NASSIGN (T_TOK * TOPK)
#define NW ((size_t)E_NUM * I_DIM * H_DIM)

// ---------------- scratch ----------------
__device__ int   g_topk_id[T_TOK][TOPK];
__device__ float g_topk_w[T_TOK][TOPK];
__device__ int   g_cnt[E_NUM];
__device__ int   g_off[E_NUM + 1];
__device__ int   g_cur[E_NUM];
__device__ int   g_slot_tok[NASSIGN];
__device__ float g_slot_w[NASSIGN];
__device__ __half g_wg_h[NW];
__device__ __half g_wu_h[NW];
__device__ __half g_wd_h[NW];
__device__ __half g_hs_h[(size_t)T_TOK * H_DIM];
__device__ __half g_act_h[NASSIGN][I_DIM];

// ---------------- PTX helpers ----------------
__device__ __forceinline__ void mma16816(float* d, const uint32_t* a, const uint32_t* b) {
    asm volatile(
        "mma.sync.aligned.m16n8k16.row.col.f32.f16.f16.f32 "
        "{%0,%1,%2,%3}, {%4,%5,%6,%7}, {%8,%9}, {%0,%1,%2,%3};"
        : "+f"(d[0]), "+f"(d[1]), "+f"(d[2]), "+f"(d[3])
        : "r"(a[0]), "r"(a[1]), "r"(a[2]), "r"(a[3]), "r"(b[0]), "r"(b[1]));
}
#define LDMX4(r, addr) \
    asm volatile("ldmatrix.sync.aligned.m8n8.x4.shared.b16 {%0,%1,%2,%3}, [%4];" \
        : "=r"((r)[0]), "=r"((r)[1]), "=r"((r)[2]), "=r"((r)[3]) : "r"(addr))
#define CP16(dst, src) \
    asm volatile("cp.async.cg.shared.global [%0], [%1], 16;" :: "r"(dst), "l"(src))
#define CP_COMMIT() asm volatile("cp.async.commit_group;" ::: "memory")
#define CP_WAIT1()  asm volatile("cp.async.wait_group 1;" ::: "memory")
#define CP_WAIT0()  asm volatile("cp.async.wait_group 0;" ::: "memory")

__device__ __forceinline__ uint32_t smem_u32(const void* p) {
    return (uint32_t)__cvta_generic_to_shared(p);
}
__device__ __forceinline__ uint4 pack8h(const float4& v0, const float4& v1) {
    __half2 h0 = __floats2half2_rn(v0.x, v0.y);
    __half2 h1 = __floats2half2_rn(v0.z, v0.w);
    __half2 h2 = __floats2half2_rn(v1.x, v1.y);
    __half2 h3 = __floats2half2_rn(v1.z, v1.w);
    uint4 o;
    o.x = *(uint32_t*)&h0; o.y = *(uint32_t*)&h1;
    o.z = *(uint32_t*)&h2; o.w = *(uint32_t*)&h3;
    return o;
}

// ------- fused convert + router: blocks [0,2048) convert, [2048,4096) route --
#define CONV_BLKS 2048
__global__ void conv_router_kernel(const float* __restrict__ wg,
                                   const float* __restrict__ wu,
                                   const float* __restrict__ wd,
                                   const float* __restrict__ hs,
                                   const float* __restrict__ gwt) {
    __shared__ float part[256][E_NUM];
    __shared__ float sl[E_NUM];
    if (blockIdx.x < CONV_BLKS) {
        if (blockIdx.x == 0 && threadIdx.x < E_NUM) {
            g_cnt[threadIdx.x] = 0;
            g_cur[threadIdx.x] = 0;
        }
        size_t nhs = (size_t)T_TOK * H_DIM;
        size_t total8 = (3 * NW + nhs) / 8;
        for (size_t i = (size_t)blockIdx.x * blockDim.x + threadIdx.x; i < total8;
             i += (size_t)CONV_BLKS * blockDim.x) {
            size_t e8 = i * 8;
            const float* src; __half* dst;
            if (e8 < NW)          { src = wg + e8;           dst = g_wg_h + e8; }
            else if (e8 < 2 * NW) { src = wu + (e8 - NW);    dst = g_wu_h + (e8 - NW); }
            else if (e8 < 3 * NW) { src = wd + (e8 - 2*NW);  dst = g_wd_h + (e8 - 2*NW); }
            else                  { src = hs + (e8 - 3*NW);  dst = g_hs_h + (e8 - 3*NW); }
            float4 v0 = *(const float4*)src;
            float4 v1 = *(const float4*)(src + 4);
            *(uint4*)dst = pack8h(v0, v1);
        }
        return;
    }
    // ---- router block ----
    int t = blockIdx.x - CONV_BLKS;
    float acc[E_NUM];
#pragma unroll
    for (int e = 0; e < E_NUM; e++) acc[e] = 0.f;
    const float* hrow = hs + (size_t)t * H_DIM;
    for (int h = threadIdx.x; h < H_DIM; h += 256) {
        float x = hrow[h];
#pragma unroll
        for (int e = 0; e < E_NUM; e++) acc[e] += x * gwt[e * H_DIM + h];
    }
#pragma unroll
    for (int e = 0; e < E_NUM; e++) part[threadIdx.x][e] = acc[e];
    __syncthreads();
    if (threadIdx.x < E_NUM) {
        float s = 0.f;
        for (int i = 0; i < 256; i++) s += part[i][threadIdx.x];
        sl[threadIdx.x] = s;
    }
    __syncthreads();
    if (threadIdx.x == 0) {
        unsigned mask = 0;
        int ids[TOPK]; float lv[TOPK];
        for (int k = 0; k < TOPK; k++) {
            float best = -3.4e38f; int bi = 0;
            for (int e = 0; e < E_NUM; e++)
                if (!((mask >> e) & 1u) && sl[e] > best) { best = sl[e]; bi = e; }
            mask |= (1u << bi); ids[k] = bi; lv[k] = best;
        }
        float mx = lv[0], s = 0.f, w[TOPK];
        for (int k = 0; k < TOPK; k++) { w[k] = expf(lv[k] - mx); s += w[k]; }
        float inv = 1.f / s;
        for (int k = 0; k < TOPK; k++) {
            g_topk_id[t][k] = ids[k];
            g_topk_w[t][k]  = w[k] * inv;
            atomicAdd(&g_cnt[ids[k]], 1);
        }
    }
}

// ---------------- scan (tiny) + parallel scatter ----------------
__global__ void scan_kernel() {
    if (threadIdx.x == 0) {
        int s = 0;
        for (int e = 0; e < E_NUM; e++) { g_off[e] = s; s += g_cnt[e]; }
        g_off[E_NUM] = s;
    }
}
__global__ void scatter_kernel() {
    int t = blockIdx.x * blockDim.x + threadIdx.x;
    if (t >= T_TOK) return;
#pragma unroll
    for (int k = 0; k < TOPK; k++) {
        int e = g_topk_id[t][k];
        int p = atomicAdd(&g_cur[e], 1);
        int s = g_off[e] + p;
        g_slot_tok[s] = t;
        g_slot_w[s]  = g_topk_w[t][k];
    }
}

// ======= gate-up GEMM: 256 thr, M128 N64(x2), KCH=64, pitch 144, 3-stage ====
// stage (bytes): A 0 (128x144=18432) | B_G 18432 (64x144=9216) | B_U 27648
#define GU_STAGE 36864
#define GU_META  (3 * GU_STAGE)
#define GU_SMEM  (GU_META + 1024)
#define GU_NCH   (H_DIM / 64)            // 32

__global__ __launch_bounds__(256, 2) void gateup_mma_kernel() {
    int e = blockIdx.z;
    int cnt = g_cnt[e];
    int m0 = blockIdx.y * 128;
    if (m0 >= cnt) return;
    int base = g_off[e];
    int n0 = blockIdx.x * 64;

    extern __shared__ char smem[];
    uint32_t sb = smem_u32(smem);
    int tid = threadIdx.x, wid = tid >> 5, lane = tid & 31;
    int g = lane >> 2, t4 = lane & 3;

    int*   stok = (int*)(smem + GU_META);
    float* swt  = (float*)(smem + GU_META + 512);
    if (tid < 128) {
        int r = m0 + tid;
        int rc = (r < cnt) ? r : (cnt - 1);
        stok[tid] = g_slot_tok[base + rc];
        swt[tid]  = (r < cnt) ? g_slot_w[base + rc] : 0.f;
    }
    __syncthreads();

    // loaders: A 2 thr/row, 64B halves; B 2 thr/row (gate tid<128, up >=128)
    int lr = tid >> 1, asel = tid & 1;
    const __half* a_src = g_hs_h + (size_t)stok[lr] * H_DIM + asel * 32;
    uint32_t aDst = sb + (uint32_t)(lr * 144 + asel * 64);
    int bt = tid & 127, br = bt >> 1, bsel = bt & 1;
    const __half* b_src = ((tid >= 128) ? g_wu_h : g_wg_h)
                          + ((size_t)e * I_DIM + n0 + br) * H_DIM + bsel * 32;
    uint32_t bDst = sb + 18432u + (tid >= 128 ? 9216u : 0u) + (uint32_t)(br * 144 + bsel * 64);

    int quad = lane >> 3, r8 = lane & 7;
    int aRow = (quad & 1) * 8 + r8, aCol = (quad >> 1) * 8;
    int bRow = (quad >> 1) * 8 + r8, bCol = (quad & 1) * 8;
    int mr = (wid & 3) * 32, nc = (wid >> 2) * 32;
    uint32_t aBase = sb + (uint32_t)((mr + aRow) * 144 + aCol * 2);
    uint32_t bBase = sb + 18432u + (uint32_t)((nc + bRow) * 144 + bCol * 2);

    float ag[2][4][4] = {}, au[2][4][4] = {};

#define GU_ISSUE(i) do { \
    uint32_t so = (uint32_t)((i) % 3) * GU_STAGE; \
    int k0 = (i) * 64; \
    CP16(aDst + so,      (const char*)(a_src + k0)); \
    CP16(aDst + so + 16, (const char*)(a_src + k0 + 8)); \
    CP16(aDst + so + 32, (const char*)(a_src + k0 + 16)); \
    CP16(aDst + so + 48, (const char*)(a_src + k0 + 24)); \
    CP16(bDst + so,      (const char*)(b_src + k0)); \
    CP16(bDst + so + 16, (const char*)(b_src + k0 + 8)); \
    CP16(bDst + so + 32, (const char*)(b_src + k0 + 16)); \
    CP16(bDst + so + 48, (const char*)(b_src + k0 + 24)); \
    CP_COMMIT(); \
} while (0)

    GU_ISSUE(0);
    GU_ISSUE(1);

    for (int i = 0; i < GU_NCH; i++) {
        if (i + 1 < GU_NCH) CP_WAIT1(); else CP_WAIT0();
        __syncthreads();
        if (i + 2 < GU_NCH) GU_ISSUE(i + 2);
        uint32_t so = (uint32_t)(i % 3) * GU_STAGE;
#pragma unroll
        for (int kb = 0; kb < 4; kb++) {
            uint32_t aH[2][4];
            uint32_t aA = aBase + so + kb * 32;
            LDMX4(aH[0], aA);
            LDMX4(aH[1], aA + 16 * 144);
#pragma unroll
            for (int p = 0; p < 2; p++) {
                uint32_t bg[4], bu[4];
                uint32_t bA = bBase + so + p * 16 * 144 + kb * 32;
                LDMX4(bg, bA);
                LDMX4(bu, bA + 9216);
#pragma unroll
                for (int s = 0; s < 2; s++) {
                    mma16816(ag[s][2 * p + 0], aH[s], bg);
                    mma16816(ag[s][2 * p + 1], aH[s], bg + 2);
                    mma16816(au[s][2 * p + 0], aH[s], bu);
                    mma16816(au[s][2 * p + 1], aH[s], bu + 2);
                }
            }
        }
        __syncthreads();
    }

#pragma unroll
    for (int s = 0; s < 2; s++) {
#pragma unroll
        for (int half = 0; half < 2; half++) {
            int rl = mr + s * 16 + g + half * 8;
            int r = m0 + rl;
            if (r < cnt) {
                float w = swt[rl];
                size_t slot = (size_t)(base + r);
#pragma unroll
                for (int nn = 0; nn < 4; nn++) {
                    float gv0 = ag[s][nn][half * 2 + 0], gv1 = ag[s][nn][half * 2 + 1];
                    float uv0 = au[s][nn][half * 2 + 0], uv1 = au[s][nn][half * 2 + 1];
                    float a0 = (gv0 / (1.f + expf(-gv0))) * uv0 * w;
                    float a1 = (gv1 / (1.f + expf(-gv1))) * uv1 * w;
                    __half2 hp = __floats2half2_rn(a0, a1);
                    int col = n0 + nc + nn * 8 + 2 * t4;
                    *(uint32_t*)&g_act_h[slot][col] = *(uint32_t*)&hp;
                }
            }
        }
    }
#undef GU_ISSUE
}

// ==== down GEMM: 256 thr, CTA 128x128, warps 4Mx2N, KCH=64, pitch 144 =======
// stage: A 0 (128x144=18432) | B 18432 (128x144=18432) ; STAGE 36864
#define DN_STAGE 36864
#define DN_META  (3 * DN_STAGE)
#define DN_SMEM  (DN_META + 512)
#define DN_NCH   (I_DIM / 64)            // 12

__global__ __launch_bounds__(256, 2) void down_mma_kernel(float* __restrict__ out) {
    int e = blockIdx.z;
    int cnt = g_cnt[e];
    int m0 = blockIdx.y * 128;
    if (m0 >= cnt) return;
    int base = g_off[e];
    int n0 = blockIdx.x * 128;

    extern __shared__ char smem[];
    uint32_t sb = smem_u32(smem);
    int tid = threadIdx.x, wid = tid >> 5, lane = tid & 31;
    int g = lane >> 2, t4 = lane & 3;
    int mr = (wid & 3) * 32, nc = (wid >> 2) * 64;

    int* stok = (int*)(smem + DN_META);
    if (tid < 128) {
        int r = m0 + tid;
        stok[tid] = (r < cnt) ? g_slot_tok[base + r] : 0;
    }
    __syncthreads();

    int lr = tid >> 1, asel = tid & 1;
    int arow_idx = base + min(m0 + lr, cnt - 1);
    const __half* a_src = &g_act_h[arow_idx][asel * 32];
    uint32_t aDst = sb + (uint32_t)(lr * 144 + asel * 64);
    const __half* b_src = g_wd_h + ((size_t)e * H_DIM + n0 + lr) * I_DIM + asel * 32;
    uint32_t bDst = sb + 18432u + (uint32_t)(lr * 144 + asel * 64);

    int quad = lane >> 3, r8 = lane & 7;
    int aRow = (quad & 1) * 8 + r8, aCol = (quad >> 1) * 8;
    int bRow = (quad >> 1) * 8 + r8, bCol = (quad & 1) * 8;
    uint32_t aBase = sb + (uint32_t)((mr + aRow) * 144 + aCol * 2);
    uint32_t bBase = sb + 18432u + (uint32_t)((nc + bRow) * 144 + bCol * 2);

    float acc[2][8][4] = {};

#define DN_ISSUE(i) do { \
    uint32_t so = (uint32_t)((i) % 3) * DN_STAGE; \
    int k0 = (i) * 64; \
    CP16(aDst + so,      (const char*)(a_src + k0)); \
    CP16(aDst + so + 16, (const char*)(a_src + k0 + 8)); \
    CP16(aDst + so + 32, (const char*)(a_src + k0 + 16)); \
    CP16(aDst + so + 48, (const char*)(a_src + k0 + 24)); \
    CP16(bDst + so,      (const char*)(b_src + k0)); \
    CP16(bDst + so + 16, (const char*)(b_src + k0 + 8)); \
    CP16(bDst + so + 32, (const char*)(b_src + k0 + 16)); \
    CP16(bDst + so + 48, (const char*)(b_src + k0 + 24)); \
    CP_COMMIT(); \
} while (0)

    DN_ISSUE(0);
    DN_ISSUE(1);

    for (int i = 0; i < DN_NCH; i++) {
        if (i + 1 < DN_NCH) CP_WAIT1(); else CP_WAIT0();
        __syncthreads();
        if (i + 2 < DN_NCH) DN_ISSUE(i + 2);
        uint32_t so = (uint32_t)(i % 3) * DN_STAGE;
#pragma unroll
        for (int kb = 0; kb < 4; kb++) {
            uint32_t aF[2][4];
            uint32_t aA = aBase + so + kb * 32;
            LDMX4(aF[0], aA);
            LDMX4(aF[1], aA + 16 * 144);
#pragma unroll
            for (int u = 0; u < 4; u++) {
                uint32_t bF[4];
                LDMX4(bF, bBase + so + u * 16 * 144 + kb * 32);
#pragma unroll
                for (int t = 0; t < 2; t++) {
                    mma16816(acc[t][2 * u + 0], aF[t], bF);
                    mma16816(acc[t][2 * u + 1], aF[t], bF + 2);
                }
            }
        }
        __syncthreads();
    }
#undef DN_ISSUE

    // epilogue: atomic accumulate
#pragma unroll
    for (int t = 0; t < 2; t++)
#pragma unroll
        for (int h = 0; h < 2; h++) {
            int lm = mr + t * 16 + g + h * 8;
            int r = m0 + lm;
            if (r < cnt) {
                int tok = stok[lm];
                float* orow = out + (size_t)tok * H_DIM + n0 + nc;
#pragma unroll
                for (int nn = 0; nn < 8; nn++) {
                    int col = nn * 8 + 2 * t4;
                    atomicAdd(&orow[col + 0], acc[t][nn][h * 2 + 0]);
                    atomicAdd(&orow[col + 1], acc[t][nn][h * 2 + 1]);
                }
            }
        }
}

// ---------------- launch ----------------
extern "C" void kernel_launch(void* const* d_in, const int* in_sizes, int n_in,
                              void* d_out, int out_size) {
    const float* hs    = (const float*)d_in[0];
    const float* gw    = (const float*)d_in[1];
    const float* wgate = (const float*)d_in[2];
    const float* wup   = (const float*)d_in[3];
    const float* wdown = (const float*)d_in[4];
    float* out = (float*)d_out;

    cudaFuncSetAttribute(gateup_mma_kernel, cudaFuncAttributeMaxDynamicSharedMemorySize, GU_SMEM);
    cudaFuncSetAttribute(down_mma_kernel,   cudaFuncAttributeMaxDynamicSharedMemorySize, DN_SMEM);

    cudaMemsetAsync(d_out, 0, (size_t)out_size * sizeof(float));
    conv_router_kernel<<<CONV_BLKS + T_TOK, 256>>>(wgate, wup, wdown, hs, gw);
    scan_kernel<<<1, 32>>>();
    scatter_kernel<<<T_TOK / 256, 256>>>();
    gateup_mma_kernel<<<dim3(I_DIM / 64, T_TOK / 128, E_NUM), 256, GU_SMEM>>>();
    down_mma_kernel  <<<dim3(H_DIM / 128, T_TOK / 128, E_NUM), 256, DN_SMEM>>>(out);
}

// round 15
// speedup vs baseline: 1.1456x; 1.1456x over previous
#include <cuda_runtime.h>
#include <cuda_fp16.h>
#include <math.h>
#include <stdint.h>

#define T_TOK 2048
#define H_DIM 2048
#define E_NUM 32
#define I_DIM 768
#define TOPK  8
#define NASSIGN (T_TOK * TOPK)
#define NW ((size_t)E_NUM * I_DIM * H_DIM)

// ---------------- scratch ----------------
__device__ int   g_topk_id[T_TOK][TOPK];
__device__ float g_topk_w[T_TOK][TOPK];
__device__ int   g_cnt[E_NUM];
__device__ int   g_off[E_NUM + 1];
__device__ int   g_cur[E_NUM];
__device__ int   g_slot_tok[NASSIGN];
__device__ float g_slot_w[NASSIGN];
__device__ __half g_wg_h[NW];
__device__ __half g_wu_h[NW];
__device__ __half g_wd_h[NW];
__device__ __half g_hs_h[(size_t)T_TOK * H_DIM];
__device__ __half g_act_h[NASSIGN][I_DIM];

// ---------------- PTX helpers ----------------
__device__ __forceinline__ void mma16816(float* d, const uint32_t* a, const uint32_t* b) {
    asm volatile(
        "mma.sync.aligned.m16n8k16.row.col.f32.f16.f16.f32 "
        "{%0,%1,%2,%3}, {%4,%5,%6,%7}, {%8,%9}, {%0,%1,%2,%3};"
        : "+f"(d[0]), "+f"(d[1]), "+f"(d[2]), "+f"(d[3])
        : "r"(a[0]), "r"(a[1]), "r"(a[2]), "r"(a[3]), "r"(b[0]), "r"(b[1]));
}
#define LDMX4(r, addr) \
    asm volatile("ldmatrix.sync.aligned.m8n8.x4.shared.b16 {%0,%1,%2,%3}, [%4];" \
        : "=r"((r)[0]), "=r"((r)[1]), "=r"((r)[2]), "=r"((r)[3]) : "r"(addr))
#define CP16(dst, src) \
    asm volatile("cp.async.cg.shared.global [%0], [%1], 16;" :: "r"(dst), "l"(src))
#define CP_COMMIT() asm volatile("cp.async.commit_group;" ::: "memory")
#define CP_WAIT1()  asm volatile("cp.async.wait_group 1;" ::: "memory")
#define CP_WAIT0()  asm volatile("cp.async.wait_group 0;" ::: "memory")

__device__ __forceinline__ uint32_t smem_u32(const void* p) {
    return (uint32_t)__cvta_generic_to_shared(p);
}
__device__ __forceinline__ uint4 pack8h(const float4& v0, const float4& v1) {
    __half2 h0 = __floats2half2_rn(v0.x, v0.y);
    __half2 h1 = __floats2half2_rn(v0.z, v0.w);
    __half2 h2 = __floats2half2_rn(v1.x, v1.y);
    __half2 h3 = __floats2half2_rn(v1.z, v1.w);
    uint4 o;
    o.x = *(uint32_t*)&h0; o.y = *(uint32_t*)&h1;
    o.z = *(uint32_t*)&h2; o.w = *(uint32_t*)&h3;
    return o;
}

// ---- fused router + convert: blocks [0,T_TOK) route, rest convert ----------
#define RT_BLKS T_TOK
#define CONV_BLKS 2048
__global__ void conv_router_kernel(const float* __restrict__ wg,
                                   const float* __restrict__ wu,
                                   const float* __restrict__ wd,
                                   const float* __restrict__ hs,
                                   const float* __restrict__ gwt) {
    __shared__ float part[256][E_NUM];
    __shared__ float sl[E_NUM];
    if (blockIdx.x >= RT_BLKS) {
        // ---- convert block ----
        int cb = blockIdx.x - RT_BLKS;
        if (cb == 0 && threadIdx.x < E_NUM) {
            g_cnt[threadIdx.x] = 0;   // router blocks atomically add; they run
            g_cur[threadIdx.x] = 0;   // in wave 1 alongside -> NOT safe. see below
        }
        size_t nhs = (size_t)T_TOK * H_DIM;
        size_t total8 = (3 * NW + nhs) / 8;
        for (size_t i = (size_t)cb * blockDim.x + threadIdx.x; i < total8;
             i += (size_t)CONV_BLKS * blockDim.x) {
            size_t e8 = i * 8;
            const float* src; __half* dst;
            if (e8 < NW)          { src = wg + e8;           dst = g_wg_h + e8; }
            else if (e8 < 2 * NW) { src = wu + (e8 - NW);    dst = g_wu_h + (e8 - NW); }
            else if (e8 < 3 * NW) { src = wd + (e8 - 2*NW);  dst = g_wd_h + (e8 - 2*NW); }
            else                  { src = hs + (e8 - 3*NW);  dst = g_hs_h + (e8 - 3*NW); }
            float4 v0 = *(const float4*)src;
            float4 v1 = *(const float4*)(src + 4);
            *(uint4*)dst = pack8h(v0, v1);
        }
        return;
    }
    // ---- router block (no atomics on g_cnt here; counts rebuilt in scan) ----
    int t = blockIdx.x;
    float acc[E_NUM];
#pragma unroll
    for (int e = 0; e < E_NUM; e++) acc[e] = 0.f;
    const float* hrow = hs + (size_t)t * H_DIM;
    for (int h = threadIdx.x; h < H_DIM; h += 256) {
        float x = hrow[h];
#pragma unroll
        for (int e = 0; e < E_NUM; e++) acc[e] += x * gwt[e * H_DIM + h];
    }
#pragma unroll
    for (int e = 0; e < E_NUM; e++) part[threadIdx.x][e] = acc[e];
    __syncthreads();
    if (threadIdx.x < E_NUM) {
        float s = 0.f;
        for (int i = 0; i < 256; i++) s += part[i][threadIdx.x];
        sl[threadIdx.x] = s;
    }
    __syncthreads();
    if (threadIdx.x == 0) {
        unsigned mask = 0;
        int ids[TOPK]; float lv[TOPK];
        for (int k = 0; k < TOPK; k++) {
            float best = -3.4e38f; int bi = 0;
            for (int e = 0; e < E_NUM; e++)
                if (!((mask >> e) & 1u) && sl[e] > best) { best = sl[e]; bi = e; }
            mask |= (1u << bi); ids[k] = bi; lv[k] = best;
        }
        float mx = lv[0], s = 0.f, w[TOPK];
        for (int k = 0; k < TOPK; k++) { w[k] = expf(lv[k] - mx); s += w[k]; }
        float inv = 1.f / s;
#pragma unroll
        for (int k = 0; k < TOPK; k++) {
            g_topk_id[t][k] = ids[k];
            g_topk_w[t][k]  = w[k] * inv;
        }
    }
}

// ------- count+scan (rebuild counts here: avoids zero/accumulate race) ------
__global__ void scan_kernel() {
    __shared__ int cnt_s[E_NUM];
    int tid = threadIdx.x;
    if (tid < E_NUM) cnt_s[tid] = 0;
    __syncthreads();
    for (int t = tid; t < T_TOK; t += 256)
#pragma unroll
        for (int k = 0; k < TOPK; k++)
            atomicAdd(&cnt_s[g_topk_id[t][k]], 1);
    __syncthreads();
    if (tid == 0) {
        int s = 0;
        for (int e = 0; e < E_NUM; e++) {
            g_cnt[e] = cnt_s[e];
            g_off[e] = s;
            g_cur[e] = 0;
            s += cnt_s[e];
        }
        g_off[E_NUM] = s;
    }
}
__global__ void scatter_kernel() {
    int t = blockIdx.x * blockDim.x + threadIdx.x;
    if (t >= T_TOK) return;
#pragma unroll
    for (int k = 0; k < TOPK; k++) {
        int e = g_topk_id[t][k];
        int p = atomicAdd(&g_cur[e], 1);
        int s = g_off[e] + p;
        g_slot_tok[s] = t;
        g_slot_w[s]  = g_topk_w[t][k];
    }
}

// ============ gate-up GEMM: R12 config (256 thr, M128 N64, KCH=32) ==========
// stage (bytes): A 0 (128x80=10240) | B_G 10240 (64x80=5120) | B_U 15360
#define GU_STAGE 20480
#define GU_META  (3 * GU_STAGE)
#define GU_SMEM  (GU_META + 1024)
#define GU_NCH   (H_DIM / 32)

__global__ __launch_bounds__(256, 2) void gateup_mma_kernel() {
    int e = blockIdx.z;
    int cnt = g_cnt[e];
    int m0 = blockIdx.y * 128;
    if (m0 >= cnt) return;
    int base = g_off[e];
    int n0 = blockIdx.x * 64;

    extern __shared__ char smem[];
    uint32_t sb = smem_u32(smem);
    int tid = threadIdx.x, wid = tid >> 5, lane = tid & 31;
    int g = lane >> 2, t4 = lane & 3;

    int*   stok = (int*)(smem + GU_META);
    float* swt  = (float*)(smem + GU_META + 512);
    if (tid < 128) {
        int r = m0 + tid;
        int rc = (r < cnt) ? r : (cnt - 1);
        stok[tid] = g_slot_tok[base + rc];
        swt[tid]  = (r < cnt) ? g_slot_w[base + rc] : 0.f;
    }
    __syncthreads();

    int lr = tid >> 1, asel = tid & 1;
    const __half* a_src = g_hs_h + (size_t)stok[lr] * H_DIM + asel * 16;
    uint32_t aDst = sb + (uint32_t)(lr * 80 + asel * 32);
    int bt = tid & 127, br = bt >> 1, bsel = bt & 1;
    const __half* b_src = ((tid >= 128) ? g_wu_h : g_wg_h)
                          + ((size_t)e * I_DIM + n0 + br) * H_DIM + bsel * 16;
    uint32_t bDst = sb + 10240u + (tid >= 128 ? 5120u : 0u) + (uint32_t)(br * 80 + bsel * 32);

    int quad = lane >> 3, r8 = lane & 7;
    int aRow = (quad & 1) * 8 + r8, aCol = (quad >> 1) * 8;
    int bRow = (quad >> 1) * 8 + r8, bCol = (quad & 1) * 8;
    int mr = (wid & 3) * 32, nc = (wid >> 2) * 32;
    uint32_t aBase = sb + (uint32_t)((mr + aRow) * 80 + aCol * 2);
    uint32_t bBase = sb + 10240u + (uint32_t)((nc + bRow) * 80 + bCol * 2);

    float ag[2][4][4] = {}, au[2][4][4] = {};

#define GU_ISSUE(i) do { \
    uint32_t so = (uint32_t)((i) % 3) * GU_STAGE; \
    int k0 = (i) * 32; \
    CP16(aDst + so,      (const char*)(a_src + k0)); \
    CP16(aDst + so + 16, (const char*)(a_src + k0 + 8)); \
    CP16(bDst + so,      (const char*)(b_src + k0)); \
    CP16(bDst + so + 16, (const char*)(b_src + k0 + 8)); \
    CP_COMMIT(); \
} while (0)

    GU_ISSUE(0);
    GU_ISSUE(1);

    for (int i = 0; i < GU_NCH; i++) {
        if (i + 1 < GU_NCH) CP_WAIT1(); else CP_WAIT0();
        __syncthreads();
        if (i + 2 < GU_NCH) GU_ISSUE(i + 2);
        uint32_t so = (uint32_t)(i % 3) * GU_STAGE;
#pragma unroll
        for (int kb = 0; kb < 2; kb++) {
            uint32_t aH[2][4];
            uint32_t aA = aBase + so + kb * 32;
            LDMX4(aH[0], aA);
            LDMX4(aH[1], aA + 16 * 80);
#pragma unroll
            for (int p = 0; p < 2; p++) {
                uint32_t bg[4], bu[4];
                uint32_t bA = bBase + so + p * 16 * 80 + kb * 32;
                LDMX4(bg, bA);
                LDMX4(bu, bA + 5120);
#pragma unroll
                for (int s = 0; s < 2; s++) {
                    mma16816(ag[s][2 * p + 0], aH[s], bg);
                    mma16816(ag[s][2 * p + 1], aH[s], bg + 2);
                    mma16816(au[s][2 * p + 0], aH[s], bu);
                    mma16816(au[s][2 * p + 1], aH[s], bu + 2);
                }
            }
        }
        __syncthreads();
    }

#pragma unroll
    for (int s = 0; s < 2; s++) {
#pragma unroll
        for (int half = 0; half < 2; half++) {
            int rl = mr + s * 16 + g + half * 8;
            int r = m0 + rl;
            if (r < cnt) {
                float w = swt[rl];
                size_t slot = (size_t)(base + r);
#pragma unroll
                for (int nn = 0; nn < 4; nn++) {
                    float gv0 = ag[s][nn][half * 2 + 0], gv1 = ag[s][nn][half * 2 + 1];
                    float uv0 = au[s][nn][half * 2 + 0], uv1 = au[s][nn][half * 2 + 1];
                    float a0 = (gv0 / (1.f + expf(-gv0))) * uv0 * w;
                    float a1 = (gv1 / (1.f + expf(-gv1))) * uv1 * w;
                    __half2 hp = __floats2half2_rn(a0, a1);
                    int col = n0 + nc + nn * 8 + 2 * t4;
                    *(uint32_t*)&g_act_h[slot][col] = *(uint32_t*)&hp;
                }
            }
        }
    }
#undef GU_ISSUE
}

// ====== down GEMM: R12 config (256 thr, CTA 128x128, warps 4Mx2N, KCH=32) ===
// stage: A[128][80]=10240 | B[128][80]=10240 ; STAGE 20480
#define DN_STAGE 20480
#define DN_META  (3 * DN_STAGE)
#define DN_SMEM  (DN_META + 512)
#define DN_NCH   (I_DIM / 32)

__global__ __launch_bounds__(256, 2) void down_mma_kernel(float* __restrict__ out) {
    int e = blockIdx.z;
    int cnt = g_cnt[e];
    int m0 = blockIdx.y * 128;
    if (m0 >= cnt) return;
    int base = g_off[e];
    int n0 = blockIdx.x * 128;

    extern __shared__ char smem[];
    uint32_t sb = smem_u32(smem);
    int tid = threadIdx.x, wid = tid >> 5, lane = tid & 31;
    int g = lane >> 2, t4 = lane & 3;
    int mr = (wid & 3) * 32, nc = (wid >> 2) * 64;

    int* stok = (int*)(smem + DN_META);
    if (tid < 128) {
        int r = m0 + tid;
        stok[tid] = (r < cnt) ? g_slot_tok[base + r] : 0;
    }
    __syncthreads();

    int lr = tid >> 1, asel = tid & 1;
    int arow_idx = base + min(m0 + lr, cnt - 1);
    const __half* a_src = &g_act_h[arow_idx][asel * 16];
    uint32_t aDst = sb + (uint32_t)(lr * 80 + asel * 32);
    const __half* b_src = g_wd_h + ((size_t)e * H_DIM + n0 + lr) * I_DIM + asel * 16;
    uint32_t bDst = sb + 10240u + (uint32_t)(lr * 80 + asel * 32);

    int quad = lane >> 3, r8 = lane & 7;
    int aRow = (quad & 1) * 8 + r8, aCol = (quad >> 1) * 8;
    int bRow = (quad >> 1) * 8 + r8, bCol = (quad & 1) * 8;
    uint32_t aBase = sb + (uint32_t)((mr + aRow) * 80 + aCol * 2);
    uint32_t bBase = sb + 10240u + (uint32_t)((nc + bRow) * 80 + bCol * 2);

    float acc[2][8][4] = {};

#define DN_ISSUE(i) do { \
    uint32_t so = (uint32_t)((i) % 3) * DN_STAGE; \
    int k0 = (i) * 32; \
    CP16(aDst + so,      (const char*)(a_src + k0)); \
    CP16(aDst + so + 16, (const char*)(a_src + k0 + 8)); \
    CP16(bDst + so,      (const char*)(b_src + k0)); \
    CP16(bDst + so + 16, (const char*)(b_src + k0 + 8)); \
    CP_COMMIT(); \
} while (0)

    DN_ISSUE(0);
    DN_ISSUE(1);

    for (int i = 0; i < DN_NCH; i++) {
        if (i + 1 < DN_NCH) CP_WAIT1(); else CP_WAIT0();
        __syncthreads();
        if (i + 2 < DN_NCH) DN_ISSUE(i + 2);
        uint32_t so = (uint32_t)(i % 3) * DN_STAGE;
#pragma unroll
        for (int kb = 0; kb < 2; kb++) {
            uint32_t aF[2][4];
            uint32_t aA = aBase + so + kb * 32;
            LDMX4(aF[0], aA);
            LDMX4(aF[1], aA + 16 * 80);
#pragma unroll
            for (int u = 0; u < 4; u++) {
                uint32_t bF[4];
                LDMX4(bF, bBase + so + u * 1280 + kb * 32);
#pragma unroll
                for (int t = 0; t < 2; t++) {
                    mma16816(acc[t][2 * u + 0], aF[t], bF);
                    mma16816(acc[t][2 * u + 1], aF[t], bF + 2);
                }
            }
        }
        __syncthreads();
    }
#undef DN_ISSUE

    // epilogue: atomic accumulate
#pragma unroll
    for (int t = 0; t < 2; t++)
#pragma unroll
        for (int h = 0; h < 2; h++) {
            int lm = mr + t * 16 + g + h * 8;
            int r = m0 + lm;
            if (r < cnt) {
                int tok = stok[lm];
                float* orow = out + (size_t)tok * H_DIM + n0 + nc;
#pragma unroll
                for (int nn = 0; nn < 8; nn++) {
                    int col = nn * 8 + 2 * t4;
                    atomicAdd(&orow[col + 0], acc[t][nn][h * 2 + 0]);
                    atomicAdd(&orow[col + 1], acc[t][nn][h * 2 + 1]);
                }
            }
        }
}

// ---------------- launch ----------------
extern "C" void kernel_launch(void* const* d_in, const int* in_sizes, int n_in,
                              void* d_out, int out_size) {
    const float* hs    = (const float*)d_in[0];
    const float* gw    = (const float*)d_in[1];
    const float* wgate = (const float*)d_in[2];
    const float* wup   = (const float*)d_in[3];
    const float* wdown = (const float*)d_in[4];
    float* out = (float*)d_out;

    cudaFuncSetAttribute(gateup_mma_kernel, cudaFuncAttributeMaxDynamicSharedMemorySize, GU_SMEM);
    cudaFuncSetAttribute(down_mma_kernel,   cudaFuncAttributeMaxDynamicSharedMemorySize, DN_SMEM);

    cudaMemsetAsync(d_out, 0, (size_t)out_size * sizeof(float));
    conv_router_kernel<<<RT_BLKS + CONV_BLKS, 256>>>(wgate, wup, wdown, hs, gw);
    scan_kernel<<<1, 256>>>();
    scatter_kernel<<<T_TOK / 256, 256>>>();
    gateup_mma_kernel<<<dim3(I_DIM / 64, T_TOK / 128, E_NUM), 256, GU_SMEM>>>();
    down_mma_kernel  <<<dim3(H_DIM / 128, T_TOK / 128, E_NUM), 256, DN_SMEM>>>(out);
}